// round 1
// baseline (speedup 1.0000x reference)
#include <cuda_runtime.h>
#include <cstddef>

// ---------------------------------------------------------------------------
// Problem constants
// ---------------------------------------------------------------------------
#define N_BATCH 64
#define M0 4096
#define M1 1024
#define K_CHEB 25
#define F0 32           // layer1 out features
#define F1 64           // layer2 out features
#define NC1 64          // layer1 state cols = N_BATCH (Fin=1)
#define NC2 2048        // layer2 state cols = N_BATCH*F0
#define SL1 (M0*NC1)    // 262144 floats per T1 slab
#define SL2 (M1*NC2)    // 2097152 floats per T2 slab

// ---------------------------------------------------------------------------
// Device scratch (no allocations allowed -> __device__ globals)
// ---------------------------------------------------------------------------
__device__ float g_T1[K_CHEB * SL1];            // 26.2 MB : layer1 cheb states [k][u][n]
__device__ float g_T2[(size_t)K_CHEB * SL2];    // 209.7MB : layer2 cheb states [k][u][n*32+f]
__device__ float g_OUT2[N_BATCH * 16384];       // 4 MB    : layer2 output, [n][u1*64+f]
__device__ float g_P[8 * N_BATCH * 512];        // 1 MB    : FC1 split-K partials
__device__ float g_Yh[N_BATCH * 512];           // FC1 output

// ---------------------------------------------------------------------------
// Transpose x (N,4096) -> T1 slab 0 as [u][n]
// ---------------------------------------------------------------------------
__global__ void transpose_x(const float* __restrict__ x, float* __restrict__ T0)
{
    __shared__ float s[32][33];
    int u0 = blockIdx.x * 32, n0 = blockIdx.y * 32;
    int tx = threadIdx.x, ty = threadIdx.y;
    for (int r = ty; r < 32; r += 8)
        s[r][tx] = x[(size_t)(n0 + r) * M0 + u0 + tx];
    __syncthreads();
    for (int r = ty; r < 32; r += 8)
        T0[(size_t)(u0 + r) * NC1 + n0 + tx] = s[tx][r];
}

// ---------------------------------------------------------------------------
// Chebyshev step GEMM:  C = s2 * (L @ B) - (hasA ? A : 0)
// L: (M x M) row-major symmetric; B,C,A: (M x NC) row-major.
// TM x TN tile, TK depth, 256 threads, MR x 4 micro-tile / thread.
// Single-stage register prefetch to hide global latency.
// ---------------------------------------------------------------------------
#define GEMM_COMPUTE()                                                        \
    do {                                                                      \
        _Pragma("unroll")                                                     \
        for (int kk = 0; kk < TK; kk++) {                                     \
            float4 b = *(const float4*)&Bs[kk][tcol];                         \
            _Pragma("unroll")                                                 \
            for (int mm = 0; mm < MR; mm++) {                                 \
                float a = Ls[kk][trow + mm];                                  \
                acc[mm][0] += a * b.x;                                        \
                acc[mm][1] += a * b.y;                                        \
                acc[mm][2] += a * b.z;                                        \
                acc[mm][3] += a * b.w;                                        \
            }                                                                 \
        }                                                                     \
    } while (0)

template<int TM, int TN, int TK, int MR, int NB4>
__global__ __launch_bounds__(256)
void cheb_gemm(const float* __restrict__ Lp, const float* __restrict__ Bp,
               const float* __restrict__ Ap, float* __restrict__ Cp,
               int M, int NC, float s2, int hasA)
{
    __shared__ float Ls[TK][TM + 4];
    __shared__ float Bs[TK][TN];

    const int tid  = threadIdx.x;
    const int u0   = blockIdx.y * TM;
    const int j0   = blockIdx.x * TN;
    const int tcol = (tid & 15) * 4;
    const int trow = (tid >> 4) * MR;

    // L loader: each thread one float4 along k (coalesced), stored transposed
    const int li = tid * 4;
    const int lu = li / TK;
    const int lk = li % TK;
    const float* Lbase = Lp + (size_t)(u0 + lu) * M + lk;

    // B loader
    int brr[NB4], bcc[NB4];
    const float* Bbase[NB4];
#pragma unroll
    for (int t = 0; t < NB4; t++) {
        int idx = tid * 4 + t * 1024;
        brr[t] = idx / TN;
        bcc[t] = idx % TN;
        Bbase[t] = Bp + (size_t)brr[t] * NC + j0 + bcc[t];
    }

    float acc[MR][4];
#pragma unroll
    for (int m = 0; m < MR; m++)
#pragma unroll
        for (int j = 0; j < 4; j++) acc[m][j] = 0.f;

    // first tile
    float4 lv = *(const float4*)(Lbase);
    float4 bv[NB4];
#pragma unroll
    for (int t = 0; t < NB4; t++) bv[t] = *(const float4*)(Bbase[t]);

    Ls[lk + 0][lu] = lv.x; Ls[lk + 1][lu] = lv.y;
    Ls[lk + 2][lu] = lv.z; Ls[lk + 3][lu] = lv.w;
#pragma unroll
    for (int t = 0; t < NB4; t++)
        *(float4*)&Bs[brr[t]][bcc[t]] = bv[t];
    __syncthreads();

    for (int k0 = TK; k0 < M; k0 += TK) {
        // prefetch next tile into registers
        lv = *(const float4*)(Lbase + k0);
#pragma unroll
        for (int t = 0; t < NB4; t++)
            bv[t] = *(const float4*)(Bbase[t] + (size_t)k0 * NC);

        GEMM_COMPUTE();
        __syncthreads();

        Ls[lk + 0][lu] = lv.x; Ls[lk + 1][lu] = lv.y;
        Ls[lk + 2][lu] = lv.z; Ls[lk + 3][lu] = lv.w;
#pragma unroll
        for (int t = 0; t < NB4; t++)
            *(float4*)&Bs[brr[t]][bcc[t]] = bv[t];
        __syncthreads();
    }
    GEMM_COMPUTE();

    // epilogue
#pragma unroll
    for (int m = 0; m < MR; m++) {
        size_t off = (size_t)(u0 + trow + m) * NC + j0 + tcol;
        float4 r;
        r.x = s2 * acc[m][0]; r.y = s2 * acc[m][1];
        r.z = s2 * acc[m][2]; r.w = s2 * acc[m][3];
        if (hasA) {
            float4 av = *(const float4*)(Ap + off);
            r.x -= av.x; r.y -= av.y; r.z -= av.z; r.w -= av.w;
        }
        *(float4*)(Cp + off) = r;
    }
}

// ---------------------------------------------------------------------------
// Layer1 tail: Y = relu( maxpool4( T1 @ W1 ) + b1 ), write as layer2 state 0
// Block: (64 n, 4 u1).  Thread computes 32 features for one (n, pooled-node).
// ---------------------------------------------------------------------------
__global__ __launch_bounds__(256)
void layer1_pool(const float* __restrict__ W1, const float* __restrict__ b1)
{
    __shared__ float W1s[K_CHEB * F0];
    __shared__ float b1s[F0];
    int n   = threadIdx.x;                       // 0..63
    int u1  = blockIdx.x * 4 + threadIdx.y;      // 0..1023
    int tid = threadIdx.y * 64 + n;

    for (int i = tid; i < K_CHEB * F0; i += 256) W1s[i] = W1[i];
    if (tid < F0) b1s[tid] = b1[tid];
    __syncthreads();

    float m[F0];
#pragma unroll
    for (int f = 0; f < F0; f++) m[f] = -1e30f;

    for (int p = 0; p < 4; p++) {
        float acc[F0];
#pragma unroll
        for (int f = 0; f < F0; f++) acc[f] = 0.f;
        int u = u1 * 4 + p;
        const float* tp = g_T1 + (size_t)u * NC1 + n;
        for (int k = 0; k < K_CHEB; k++) {
            float t = tp[(size_t)k * SL1];
#pragma unroll
            for (int f = 0; f < F0; f++) acc[f] += t * W1s[k * F0 + f];
        }
#pragma unroll
        for (int f = 0; f < F0; f++) m[f] = fmaxf(m[f], acc[f]);
    }
    float* op = g_T2 + (size_t)u1 * NC2 + n * F0;
#pragma unroll
    for (int f = 0; f < F0; f++) op[f] = fmaxf(m[f] + b1s[f], 0.f);
}

// ---------------------------------------------------------------------------
// Layer2 tail: OUT2 = relu( maxpool4( T2_features @ W2 ) + b2 )
// Block (64 n, 2 u1), grid (128 u1-pairs, 2 f-halves).
// W2 half (800 x 32) staged once in dynamic smem (100 KB).
// ---------------------------------------------------------------------------
__global__ __launch_bounds__(128)
void layer2_pool(const float* __restrict__ W2, const float* __restrict__ b2)
{
    extern __shared__ float Wall[];              // [800][32] for this f-half
    int n   = threadIdx.x;                       // 0..63
    int u1  = blockIdx.x * 2 + threadIdx.y;      // 0..255
    int f0  = blockIdx.y * 32;
    int tid = threadIdx.y * 64 + n;

    for (int i = tid; i < 800 * 32; i += 128) {
        int r = i >> 5, f = i & 31;
        Wall[i] = W2[(size_t)r * F1 + f0 + f];
    }
    __syncthreads();

    float m[32];
#pragma unroll
    for (int f = 0; f < 32; f++) m[f] = -1e30f;

    for (int p = 0; p < 4; p++) {
        float acc[32];
#pragma unroll
        for (int f = 0; f < 32; f++) acc[f] = 0.f;
        int u = u1 * 4 + p;
        for (int k = 0; k < K_CHEB; k++) {
            const float4* tp = (const float4*)(g_T2 + (size_t)k * SL2 +
                                               (size_t)u * NC2 + n * F0);
#pragma unroll
            for (int c4 = 0; c4 < 8; c4++) {
                float4 t = tp[c4];
                const float* w0 = &Wall[((c4 * 4 + 0) * K_CHEB + k) * 32];
                const float* w1 = &Wall[((c4 * 4 + 1) * K_CHEB + k) * 32];
                const float* w2 = &Wall[((c4 * 4 + 2) * K_CHEB + k) * 32];
                const float* w3 = &Wall[((c4 * 4 + 3) * K_CHEB + k) * 32];
#pragma unroll
                for (int f = 0; f < 32; f++) {
                    acc[f] += t.x * w0[f];
                    acc[f] += t.y * w1[f];
                    acc[f] += t.z * w2[f];
                    acc[f] += t.w * w3[f];
                }
            }
        }
#pragma unroll
        for (int f = 0; f < 32; f++) m[f] = fmaxf(m[f], acc[f]);
    }
    float* op = g_OUT2 + (size_t)n * 16384 + u1 * F1 + f0;
#pragma unroll
    for (int f = 0; f < 32; f++) op[f] = fmaxf(m[f] + b2[f0 + f], 0.f);
}

// ---------------------------------------------------------------------------
// FC1 split-K partial: P[z][n][j] = sum_{k in z-range} OUT2[n][k]*Wh[k][j]
// grid (16 j-tiles, 8 z), block 256.
// ---------------------------------------------------------------------------
__global__ __launch_bounds__(256)
void fc1_partial(const float* __restrict__ Wh)
{
    __shared__ float As[32][68];
    __shared__ float Ws[32][32];
    int tid  = threadIdx.x;
    int j0   = blockIdx.x * 32;
    int kz   = blockIdx.y * 2048;
    int tcol = tid & 31;
    int n0   = (tid >> 5) * 8;
    float acc[8];
#pragma unroll
    for (int i = 0; i < 8; i++) acc[i] = 0.f;

    for (int k0 = 0; k0 < 2048; k0 += 32) {
        __syncthreads();
#pragma unroll
        for (int it = 0; it < 2; it++) {
            int idx = tid * 4 + it * 1024;
            int nn = idx >> 5;
            int kk = idx & 31;
            float4 v = *(const float4*)(g_OUT2 + (size_t)nn * 16384 + kz + k0 + kk);
            As[kk + 0][nn] = v.x; As[kk + 1][nn] = v.y;
            As[kk + 2][nn] = v.z; As[kk + 3][nn] = v.w;
        }
#pragma unroll
        for (int i = tid; i < 1024; i += 256) {
            int r = i >> 5, c = i & 31;
            Ws[r][c] = Wh[(size_t)(kz + k0 + r) * 512 + j0 + c];
        }
        __syncthreads();
#pragma unroll
        for (int kk = 0; kk < 32; kk++) {
            float w = Ws[kk][tcol];
            float4 a0 = *(const float4*)&As[kk][n0];
            float4 a1 = *(const float4*)&As[kk][n0 + 4];
            acc[0] += a0.x * w; acc[1] += a0.y * w;
            acc[2] += a0.z * w; acc[3] += a0.w * w;
            acc[4] += a1.x * w; acc[5] += a1.y * w;
            acc[6] += a1.z * w; acc[7] += a1.w * w;
        }
    }
#pragma unroll
    for (int i = 0; i < 8; i++)
        g_P[(size_t)blockIdx.y * 32768 + (size_t)(n0 + i) * 512 + j0 + tcol] = acc[i];
}

__global__ void fc1_reduce(const float* __restrict__ bh)
{
    int i = blockIdx.x * blockDim.x + threadIdx.x;   // < 32768
    float s = 0.f;
#pragma unroll
    for (int z = 0; z < 8; z++) s += g_P[(size_t)z * 32768 + i];
    g_Yh[i] = fmaxf(s + bh[i & 511], 0.f);
}

__global__ void fc2(const float* __restrict__ Wo, const float* __restrict__ bo,
                    float* __restrict__ out)
{
    int g = blockIdx.x * blockDim.x + threadIdx.x;
    if (g >= 640) return;
    int n = g / 10, o = g % 10;
    float s = bo[o];
    const float* y = g_Yh + (size_t)n * 512;
    for (int j = 0; j < 512; j++) s += y[j] * Wo[j * 10 + o];
    out[g] = s;
}

// ---------------------------------------------------------------------------
// Host driver
// ---------------------------------------------------------------------------
extern "C" void kernel_launch(void* const* d_in, const int* in_sizes, int n_in,
                              void* d_out, int out_size)
{
    const float* x  = (const float*)d_in[0];
    const float* L0 = (const float*)d_in[1];
    const float* L1 = (const float*)d_in[2];
    const float* W1 = (const float*)d_in[3];
    const float* b1 = (const float*)d_in[4];
    const float* W2 = (const float*)d_in[5];
    const float* b2 = (const float*)d_in[6];
    const float* Wh = (const float*)d_in[7];
    const float* bh = (const float*)d_in[8];
    const float* Wo = (const float*)d_in[9];
    const float* bo = (const float*)d_in[10];
    float* out = (float*)d_out;

    float *T1p, *T2p;
    cudaGetSymbolAddress((void**)&T1p, g_T1);
    cudaGetSymbolAddress((void**)&T2p, g_T2);

    // ---- layer 1 Chebyshev recurrence ----
    transpose_x<<<dim3(M0 / 32, N_BATCH / 32), dim3(32, 8)>>>(x, T1p);

    cheb_gemm<32, 64, 32, 2, 2><<<dim3(1, M0 / 32), 256>>>(
        L0, T1p, nullptr, T1p + SL1, M0, NC1, 1.f, 0);
    for (int k = 2; k < K_CHEB; k++)
        cheb_gemm<32, 64, 32, 2, 2><<<dim3(1, M0 / 32), 256>>>(
            L0, T1p + (size_t)(k - 1) * SL1, T1p + (size_t)(k - 2) * SL1,
            T1p + (size_t)k * SL1, M0, NC1, 2.f, 1);

    // ---- layer 1 contraction + relu + pool -> layer2 state 0 ----
    layer1_pool<<<M1, dim3(64, 4)>>>(W1, b1);

    // ---- layer 2 Chebyshev recurrence ----
    cheb_gemm<64, 64, 16, 4, 1><<<dim3(NC2 / 64, M1 / 64), 256>>>(
        L1, T2p, nullptr, T2p + SL2, M1, NC2, 1.f, 0);
    for (int k = 2; k < K_CHEB; k++)
        cheb_gemm<64, 64, 16, 4, 1><<<dim3(NC2 / 64, M1 / 64), 256>>>(
            L1, T2p + (size_t)(k - 1) * SL2, T2p + (size_t)(k - 2) * SL2,
            T2p + (size_t)k * SL2, M1, NC2, 2.f, 1);

    // ---- layer 2 contraction + relu + pool ----
    cudaFuncSetAttribute(layer2_pool, cudaFuncAttributeMaxDynamicSharedMemorySize,
                         800 * 32 * 4);
    layer2_pool<<<dim3(128, 2), dim3(64, 2), 800 * 32 * 4>>>(W2, b2);

    // ---- FC head ----
    fc1_partial<<<dim3(16, 8), 256>>>(Wh);
    fc1_reduce<<<128, 256>>>(bh);
    fc2<<<5, 128>>>(Wo, bo, out);
}